// round 7
// baseline (speedup 1.0000x reference)
#include <cuda_runtime.h>
#include <math.h>

#define NPTS   100000
#define NSAMP  16
#define NELEM  (NPTS*NSAMP)
#define CC     64
#define CWW    8
#define EPSV   1e-5

// ---------------- device scratch (static globals: allowed) ----------------
__device__ float  g_xq[NPTS*CC];     // 25.6 MB
__device__ float  g_xk[NPTS*CC];     // 25.6 MB
__device__ float  g_xv[NPTS*CC];     // 25.6 MB
__device__ float  g_t [NELEM*CWW];   // 51.2 MB
__device__ double g_stats[150];
// layout: [0:3) s1  [3:6) q1  [6:70) s2  [70:134) q2  [134:142) s3  [142:150) q3

__global__ void k_zero() {
    if (threadIdx.x < 150) g_stats[threadIdx.x] = 0.0;
}

// finalize BN stats -> affine (A,B):  bn(x) = x*A + B, computed in double
__device__ __forceinline__ void bn_affine_shared(int tid, int nch, int soff, int qoff,
        const float* __restrict__ gamma, const float* __restrict__ beta,
        float* sA, float* sB)
{
    if (tid < nch) {
        double m   = g_stats[soff + tid] * (1.0 / (double)NELEM);
        double v   = g_stats[qoff + tid] * (1.0 / (double)NELEM) - m * m;
        double inv = 1.0 / sqrt(v + (double)EPSV);
        double g   = (double)__ldg(gamma + tid);
        sA[tid] = (float)(g * inv);
        sB[tid] = (float)((double)__ldg(beta + tid) - m * inv * g);
    }
}

// ---------------- K1: fused QKV GEMM ----------------
__device__ __forceinline__ void qkv_phase(const float (*xs)[CC], float (*Ws)[CC],
        const float* __restrict__ W, const float* __restrict__ B,
        float* __restrict__ OUT, int n, int pt, int cg, int tid)
{
    __syncthreads();
    for (int i = tid; i < CC*CC; i += 256) (&Ws[0][0])[i] = __ldg(W + i);
    __syncthreads();
    float acc[8];
    #pragma unroll
    for (int j = 0; j < 8; j++) acc[j] = __ldg(B + cg + j);
    #pragma unroll 8
    for (int k = 0; k < CC; k++) {
        float xv = xs[pt][k];
        float4 wa = *(const float4*)&Ws[k][cg];
        float4 wb = *(const float4*)&Ws[k][cg+4];
        acc[0] = fmaf(xv, wa.x, acc[0]); acc[1] = fmaf(xv, wa.y, acc[1]);
        acc[2] = fmaf(xv, wa.z, acc[2]); acc[3] = fmaf(xv, wa.w, acc[3]);
        acc[4] = fmaf(xv, wb.x, acc[4]); acc[5] = fmaf(xv, wb.y, acc[5]);
        acc[6] = fmaf(xv, wb.z, acc[6]); acc[7] = fmaf(xv, wb.w, acc[7]);
    }
    float4* o = (float4*)(OUT + (size_t)n*CC + cg);
    o[0] = make_float4(acc[0], acc[1], acc[2], acc[3]);
    o[1] = make_float4(acc[4], acc[5], acc[6], acc[7]);
}

__global__ void __launch_bounds__(256) k_qkv(const float* __restrict__ x,
        const float* __restrict__ Wq, const float* __restrict__ bq,
        const float* __restrict__ Wk, const float* __restrict__ bk,
        const float* __restrict__ Wv, const float* __restrict__ bv)
{
    __shared__ float xs[32][CC];
    __shared__ float Ws[CC][CC];
    const int tid = threadIdx.x;
    const int n0  = blockIdx.x * 32;
    for (int i = tid; i < 32*CC; i += 256)
        xs[i >> 6][i & 63] = __ldg(x + (size_t)(n0 + (i >> 6))*CC + (i & 63));
    const int pt = tid >> 3;
    const int cg = (tid & 7) << 3;
    const int n  = n0 + pt;
    qkv_phase(xs, Ws, Wq, bq, g_xq, n, pt, cg, tid);
    qkv_phase(xs, Ws, Wk, bk, g_xk, n, pt, cg, tid);
    qkv_phase(xs, Ws, Wv, bv, g_xv, n, pt, cg, tid);
}

// ---------------- K2: BN1 stats (3 channels of (p[idx]-p)@Wp1+bp1) ----------------
__global__ void __launch_bounds__(256) k_stats1(const float* __restrict__ p,
        const int* __restrict__ idx,
        const float* __restrict__ Wp1, const float* __restrict__ bp1)
{
    float w[9], b[3];
    #pragma unroll
    for (int i = 0; i < 9; i++) w[i] = __ldg(Wp1 + i);
    #pragma unroll
    for (int i = 0; i < 3; i++) b[i] = __ldg(bp1 + i);
    float s0=0.f,s1=0.f,s2=0.f,q0=0.f,q1=0.f,q2=0.f;
    const int stride = gridDim.x * blockDim.x;
    for (int e = blockIdx.x*blockDim.x + threadIdx.x; e < NELEM; e += stride) {
        int n = e >> 4;
        int j = __ldg(idx + e);
        float dx = __ldg(p + j*3 + 0) - __ldg(p + n*3 + 0);
        float dy = __ldg(p + j*3 + 1) - __ldg(p + n*3 + 1);
        float dz = __ldg(p + j*3 + 2) - __ldg(p + n*3 + 2);
        float h0 = fmaf(dx, w[0], fmaf(dy, w[3], fmaf(dz, w[6], b[0])));
        float h1 = fmaf(dx, w[1], fmaf(dy, w[4], fmaf(dz, w[7], b[1])));
        float h2 = fmaf(dx, w[2], fmaf(dy, w[5], fmaf(dz, w[8], b[2])));
        s0 += h0; q0 += h0*h0;
        s1 += h1; q1 += h1*h1;
        s2 += h2; q2 += h2*h2;
    }
    #pragma unroll
    for (int off = 16; off; off >>= 1) {
        s0 += __shfl_down_sync(0xffffffffu, s0, off); q0 += __shfl_down_sync(0xffffffffu, q0, off);
        s1 += __shfl_down_sync(0xffffffffu, s1, off); q1 += __shfl_down_sync(0xffffffffu, q1, off);
        s2 += __shfl_down_sync(0xffffffffu, s2, off); q2 += __shfl_down_sync(0xffffffffu, q2, off);
    }
    __shared__ double sh[6];
    if (threadIdx.x < 6) sh[threadIdx.x] = 0.0;
    __syncthreads();
    if ((threadIdx.x & 31) == 0) {
        atomicAdd(&sh[0], (double)s0); atomicAdd(&sh[1], (double)s1); atomicAdd(&sh[2], (double)s2);
        atomicAdd(&sh[3], (double)q0); atomicAdd(&sh[4], (double)q1); atomicAdd(&sh[5], (double)q2);
    }
    __syncthreads();
    if (threadIdx.x < 6) atomicAdd(&g_stats[threadIdx.x], sh[threadIdx.x]);
}

// ---------------- K3: BN2 stats over r_qk (channel-group split via blockIdx.y) ----------------
__global__ void __launch_bounds__(256) k_stats2(
        const float* __restrict__ p, const int* __restrict__ idx,
        const float* __restrict__ Wp1, const float* __restrict__ bp1,
        const float* __restrict__ gp, const float* __restrict__ betap,
        const float* __restrict__ Wp2, const float* __restrict__ bp2)
{
    const int tid = threadIdx.x;
    const int cg  = blockIdx.y * 8;
    __shared__ float sA1[3], sB1[3];
    bn_affine_shared(tid, 3, 0, 3, gp, betap, sA1, sB1);
    __syncthreads();
    const float A1x=sA1[0], A1y=sA1[1], A1z=sA1[2];
    const float B1x=sB1[0], B1y=sB1[1], B1z=sB1[2];
    float w[9], b1r[3];
    #pragma unroll
    for (int i = 0; i < 9; i++) w[i] = __ldg(Wp1 + i);
    #pragma unroll
    for (int i = 0; i < 3; i++) b1r[i] = __ldg(bp1 + i);
    float p20[8], p21[8], p22[8], pbv[8];
    #pragma unroll
    for (int s = 0; s < 8; s++) {
        int c = cg + s;
        p20[s] = __ldg(Wp2 + c);       p21[s] = __ldg(Wp2 + 64 + c);
        p22[s] = __ldg(Wp2 + 128 + c); pbv[s] = __ldg(bp2 + c);
    }
    float sacc[8] = {0,0,0,0,0,0,0,0}, qacc[8] = {0,0,0,0,0,0,0,0};
    const int stride = gridDim.x * blockDim.x;
    for (int e = blockIdx.x*blockDim.x + tid; e < NELEM; e += stride) {
        int nn = e >> 4;
        int j  = __ldg(idx + e);
        float dx = __ldg(p + j*3 + 0) - __ldg(p + nn*3 + 0);
        float dy = __ldg(p + j*3 + 1) - __ldg(p + nn*3 + 1);
        float dz = __ldg(p + j*3 + 2) - __ldg(p + nn*3 + 2);
        float h0 = fmaf(dx, w[0], fmaf(dy, w[3], fmaf(dz, w[6], b1r[0])));
        float h1 = fmaf(dx, w[1], fmaf(dy, w[4], fmaf(dz, w[7], b1r[1])));
        float h2 = fmaf(dx, w[2], fmaf(dy, w[5], fmaf(dz, w[8], b1r[2])));
        float a0 = fmaxf(fmaf(h0, A1x, B1x), 0.f);
        float a1 = fmaxf(fmaf(h1, A1y, B1y), 0.f);
        float a2 = fmaxf(fmaf(h2, A1z, B1z), 0.f);
        const float4 k0  = *(const float4*)(g_xk + (size_t)j*CC + cg);
        const float4 k1  = *(const float4*)(g_xk + (size_t)j*CC + cg + 4);
        const float4 xq0 = *(const float4*)(g_xq + (size_t)nn*CC + cg);
        const float4 xq1 = *(const float4*)(g_xq + (size_t)nn*CC + cg + 4);
        float kv[8] = {k0.x,k0.y,k0.z,k0.w,k1.x,k1.y,k1.z,k1.w};
        float qv[8] = {xq0.x,xq0.y,xq0.z,xq0.w,xq1.x,xq1.y,xq1.z,xq1.w};
        #pragma unroll
        for (int s = 0; s < 8; s++) {
            float r = kv[s] - qv[s] + fmaf(a0, p20[s], fmaf(a1, p21[s], fmaf(a2, p22[s], pbv[s])));
            sacc[s] += r; qacc[s] += r*r;
        }
    }
    #pragma unroll
    for (int s = 0; s < 8; s++) {
        #pragma unroll
        for (int off = 16; off; off >>= 1) {
            sacc[s] += __shfl_down_sync(0xffffffffu, sacc[s], off);
            qacc[s] += __shfl_down_sync(0xffffffffu, qacc[s], off);
        }
    }
    __shared__ double sh[16];
    if (tid < 16) sh[tid] = 0.0;
    __syncthreads();
    if ((tid & 31) == 0) {
        #pragma unroll
        for (int s = 0; s < 8; s++) {
            atomicAdd(&sh[s],   (double)sacc[s]);
            atomicAdd(&sh[8+s], (double)qacc[s]);
        }
    }
    __syncthreads();
    if (tid < 8)       atomicAdd(&g_stats[6  + cg + tid],     sh[tid]);
    else if (tid < 16) atomicAdd(&g_stats[70 + cg + tid - 8], sh[tid]);
}

// ---------------- K4: t = relu(bn2(r_qk)) @ Ww1 + bww1 ; BN3 stats ----------------
__global__ void __launch_bounds__(256) k_proj(
        const float* __restrict__ p, const int* __restrict__ idx,
        const float* __restrict__ Wp1, const float* __restrict__ bp1,
        const float* __restrict__ gp, const float* __restrict__ betap,
        const float* __restrict__ Wp2, const float* __restrict__ bp2,
        const float* __restrict__ gw1, const float* __restrict__ bw1,
        const float* __restrict__ Ww1, const float* __restrict__ bww1)
{
    const int tid = threadIdx.x;
    __shared__ float  sA1[3], sB1[3];
    __shared__ float4 sP2[64];
    __shared__ float2 sAB[64];
    __shared__ float4 sW1[64][2];
    bn_affine_shared(tid, 3, 0, 3, gp, betap, sA1, sB1);
    if (tid < 64) {
        sP2[tid] = make_float4(__ldg(Wp2 + tid), __ldg(Wp2 + 64 + tid),
                               __ldg(Wp2 + 128 + tid), __ldg(bp2 + tid));
        double m   = g_stats[6 + tid]  * (1.0 / (double)NELEM);
        double v   = g_stats[70 + tid] * (1.0 / (double)NELEM) - m*m;
        double inv = 1.0 / sqrt(v + (double)EPSV);
        double g   = (double)__ldg(gw1 + tid);
        sAB[tid] = make_float2((float)(g * inv), (float)((double)__ldg(bw1 + tid) - m*inv*g));
        sW1[tid][0] = *(const float4*)(Ww1 + tid*8);
        sW1[tid][1] = *(const float4*)(Ww1 + tid*8 + 4);
    }
    __syncthreads();
    const float A1x=sA1[0], A1y=sA1[1], A1z=sA1[2];
    const float B1x=sB1[0], B1y=sB1[1], B1z=sB1[2];
    float w[9], b1r[3];
    #pragma unroll
    for (int i = 0; i < 9; i++) w[i] = __ldg(Wp1 + i);
    #pragma unroll
    for (int i = 0; i < 3; i++) b1r[i] = __ldg(bp1 + i);
    float bias3[8];
    #pragma unroll
    for (int i = 0; i < 8; i++) bias3[i] = __ldg(bww1 + i);

    float s3[8] = {0,0,0,0,0,0,0,0}, q3[8] = {0,0,0,0,0,0,0,0};
    const int stride = gridDim.x * blockDim.x;
    for (int e = blockIdx.x*blockDim.x + tid; e < NELEM; e += stride) {
        int nn = e >> 4;
        int j  = __ldg(idx + e);
        float dx = __ldg(p + j*3 + 0) - __ldg(p + nn*3 + 0);
        float dy = __ldg(p + j*3 + 1) - __ldg(p + nn*3 + 1);
        float dz = __ldg(p + j*3 + 2) - __ldg(p + nn*3 + 2);
        float h0 = fmaf(dx, w[0], fmaf(dy, w[3], fmaf(dz, w[6], b1r[0])));
        float h1 = fmaf(dx, w[1], fmaf(dy, w[4], fmaf(dz, w[7], b1r[1])));
        float h2 = fmaf(dx, w[2], fmaf(dy, w[5], fmaf(dz, w[8], b1r[2])));
        float a0 = fmaxf(fmaf(h0, A1x, B1x), 0.f);
        float a1 = fmaxf(fmaf(h1, A1y, B1y), 0.f);
        float a2 = fmaxf(fmaf(h2, A1z, B1z), 0.f);
        float acc[8];
        #pragma unroll
        for (int i = 0; i < 8; i++) acc[i] = bias3[i];
        const float* kp = g_xk + (size_t)j*CC;
        const float* qp = g_xq + (size_t)nn*CC;
#define CH(CIDX, KV, QV) do { \
        float4 pc = sP2[CIDX]; \
        float r = (KV) - (QV) + fmaf(a0, pc.x, fmaf(a1, pc.y, fmaf(a2, pc.z, pc.w))); \
        float2 ab = sAB[CIDX]; \
        float y = fmaxf(fmaf(r, ab.x, ab.y), 0.f); \
        float4 wA = sW1[CIDX][0], wB = sW1[CIDX][1]; \
        acc[0]=fmaf(y,wA.x,acc[0]); acc[1]=fmaf(y,wA.y,acc[1]); \
        acc[2]=fmaf(y,wA.z,acc[2]); acc[3]=fmaf(y,wA.w,acc[3]); \
        acc[4]=fmaf(y,wB.x,acc[4]); acc[5]=fmaf(y,wB.y,acc[5]); \
        acc[6]=fmaf(y,wB.z,acc[6]); acc[7]=fmaf(y,wB.w,acc[7]); \
    } while (0)
        #pragma unroll
        for (int cb = 0; cb < CC; cb += 4) {
            const float4 k4 = *(const float4*)(kp + cb);
            const float4 q4 = *(const float4*)(qp + cb);
            CH(cb+0, k4.x, q4.x);
            CH(cb+1, k4.y, q4.y);
            CH(cb+2, k4.z, q4.z);
            CH(cb+3, k4.w, q4.w);
        }
#undef CH
        *(float4*)(g_t + (size_t)e*8)     = make_float4(acc[0], acc[1], acc[2], acc[3]);
        *(float4*)(g_t + (size_t)e*8 + 4) = make_float4(acc[4], acc[5], acc[6], acc[7]);
        #pragma unroll
        for (int i = 0; i < 8; i++) { s3[i] += acc[i]; q3[i] += acc[i]*acc[i]; }
    }
    #pragma unroll
    for (int i = 0; i < 8; i++) {
        #pragma unroll
        for (int off = 16; off; off >>= 1) {
            s3[i] += __shfl_down_sync(0xffffffffu, s3[i], off);
            q3[i] += __shfl_down_sync(0xffffffffu, q3[i], off);
        }
    }
    __shared__ double sh3[16];
    if (tid < 16) sh3[tid] = 0.0;
    __syncthreads();
    if ((tid & 31) == 0) {
        #pragma unroll
        for (int i = 0; i < 8; i++) {
            atomicAdd(&sh3[i],   (double)s3[i]);
            atomicAdd(&sh3[8+i], (double)q3[i]);
        }
    }
    __syncthreads();
    if (tid < 16) atomicAdd(&g_stats[134 + tid], sh3[tid]);
}

// ---------------- K5: logits -> softmax over NS -> weighted sum -> out ----------------
__global__ void __launch_bounds__(256) k_out(
        const float* __restrict__ p, const int* __restrict__ idx,
        const float* __restrict__ Wp1, const float* __restrict__ bp1,
        const float* __restrict__ gp, const float* __restrict__ betap,
        const float* __restrict__ Wp2, const float* __restrict__ bp2,
        const float* __restrict__ gw2, const float* __restrict__ bw2,
        const float* __restrict__ Ww2, const float* __restrict__ bww2,
        float* __restrict__ out)
{
    const int tid  = threadIdx.x;
    const int lane = tid & 31;
    const int warp = tid >> 5;             // 0..7 -> point within block
    const int n    = blockIdx.x * 8 + warp;
    const int ci   = lane >> 2;            // attention channel 0..7
    const int tq   = lane & 3;             // neighbor quarter

    __shared__ float sA1[3], sB1[3], sA3[8], sB3[8];
    bn_affine_shared(tid, 3, 0, 3, gp, betap, sA1, sB1);
    bn_affine_shared(tid, 8, 134, 142, gw2, bw2, sA3, sB3);
    __syncthreads();
    const float A1x=sA1[0], A1y=sA1[1], A1z=sA1[2];
    const float B1x=sB1[0], B1y=sB1[1], B1z=sB1[2];
    float A3[8], B3[8], w2c[8];
    #pragma unroll
    for (int k = 0; k < 8; k++) {
        A3[k] = sA3[k]; B3[k] = sB3[k];
        w2c[k] = __ldg(Ww2 + k*8 + ci);
    }
    const float bw2c = __ldg(bww2 + ci);
    float w1r[9], b1r[3];
    #pragma unroll
    for (int i = 0; i < 9; i++) w1r[i] = __ldg(Wp1 + i);
    #pragma unroll
    for (int i = 0; i < 3; i++) b1r[i] = __ldg(bp1 + i);
    float p20[8], p21[8], p22[8], pbv[8];
    #pragma unroll
    for (int s = 0; s < 8; s++) {
        int c = s*8 + ci;
        p20[s] = __ldg(Wp2 + c);       p21[s] = __ldg(Wp2 + 64 + c);
        p22[s] = __ldg(Wp2 + 128 + c); pbv[s] = __ldg(bp2 + c);
    }
    const float px = __ldg(p + n*3 + 0), py = __ldg(p + n*3 + 1), pz = __ldg(p + n*3 + 2);

    int   js[4];
    float a0s[4], a1s[4], a2s[4], L[4];
    #pragma unroll
    for (int u = 0; u < 4; u++) {
        int t = tq*4 + u;
        int e = n*16 + t;
        int j = __ldg(idx + e);
        js[u] = j;
        float dx = __ldg(p + j*3 + 0) - px;
        float dy = __ldg(p + j*3 + 1) - py;
        float dz = __ldg(p + j*3 + 2) - pz;
        float h0 = fmaf(dx, w1r[0], fmaf(dy, w1r[3], fmaf(dz, w1r[6], b1r[0])));
        float h1 = fmaf(dx, w1r[1], fmaf(dy, w1r[4], fmaf(dz, w1r[7], b1r[1])));
        float h2 = fmaf(dx, w1r[2], fmaf(dy, w1r[5], fmaf(dz, w1r[8], b1r[2])));
        a0s[u] = fmaxf(fmaf(h0, A1x, B1x), 0.f);
        a1s[u] = fmaxf(fmaf(h1, A1y, B1y), 0.f);
        a2s[u] = fmaxf(fmaf(h2, A1z, B1z), 0.f);
        const float4 ta = *(const float4*)(g_t + (size_t)e*8);
        const float4 tb = *(const float4*)(g_t + (size_t)e*8 + 4);
        float lg = bw2c;
        lg = fmaf(fmaxf(fmaf(ta.x, A3[0], B3[0]), 0.f), w2c[0], lg);
        lg = fmaf(fmaxf(fmaf(ta.y, A3[1], B3[1]), 0.f), w2c[1], lg);
        lg = fmaf(fmaxf(fmaf(ta.z, A3[2], B3[2]), 0.f), w2c[2], lg);
        lg = fmaf(fmaxf(fmaf(ta.w, A3[3], B3[3]), 0.f), w2c[3], lg);
        lg = fmaf(fmaxf(fmaf(tb.x, A3[4], B3[4]), 0.f), w2c[4], lg);
        lg = fmaf(fmaxf(fmaf(tb.y, A3[5], B3[5]), 0.f), w2c[5], lg);
        lg = fmaf(fmaxf(fmaf(tb.z, A3[6], B3[6]), 0.f), w2c[6], lg);
        lg = fmaf(fmaxf(fmaf(tb.w, A3[7], B3[7]), 0.f), w2c[7], lg);
        L[u] = lg;
    }
    // softmax over 16 neighbors per (n, ci): lanes {ci*4 .. ci*4+3}
    float mx = fmaxf(fmaxf(L[0], L[1]), fmaxf(L[2], L[3]));
    mx = fmaxf(mx, __shfl_xor_sync(0xffffffffu, mx, 1));
    mx = fmaxf(mx, __shfl_xor_sync(0xffffffffu, mx, 2));
    float sum = 0.f;
    #pragma unroll
    for (int u = 0; u < 4; u++) { L[u] = expf(L[u] - mx); sum += L[u]; }
    sum += __shfl_xor_sync(0xffffffffu, sum, 1);
    sum += __shfl_xor_sync(0xffffffffu, sum, 2);
    const float rs = 1.f / sum;

    float acc[8] = {0,0,0,0,0,0,0,0};
    #pragma unroll
    for (int u = 0; u < 4; u++) {
        float wv = L[u] * rs;
        const float* xr = g_xv + (size_t)js[u]*CC;
        float a0 = a0s[u], a1 = a1s[u], a2 = a2s[u];
        #pragma unroll
        for (int s = 0; s < 8; s++) {
            float pr = fmaf(a0, p20[s], fmaf(a1, p21[s], fmaf(a2, p22[s], pbv[s])));
            acc[s] = fmaf(__ldg(xr + s*8 + ci) + pr, wv, acc[s]);
        }
    }
    #pragma unroll
    for (int s = 0; s < 8; s++) {
        acc[s] += __shfl_xor_sync(0xffffffffu, acc[s], 1);
        acc[s] += __shfl_xor_sync(0xffffffffu, acc[s], 2);
    }
    __shared__ float smout[8][64];
    if (tq == 0) {
        #pragma unroll
        for (int s = 0; s < 8; s++) smout[warp][s*8 + ci] = acc[s];
    }
    __syncthreads();
    const int nb = blockIdx.x * 8;
    for (int i2 = tid; i2 < 8*64; i2 += 256)
        out[(size_t)nb*64 + i2] = (&smout[0][0])[i2];
}

// ---------------- host ----------------
extern "C" void kernel_launch(void* const* d_in, const int* in_sizes, int n_in,
                              void* d_out, int out_size)
{
    const float* p     = (const float*)d_in[0];
    const float* x     = (const float*)d_in[1];
    /* d_in[2] = o (unused) */
    const int*   idx   = (const int*)  d_in[3];
    const float* Wq    = (const float*)d_in[4];
    const float* bq    = (const float*)d_in[5];
    const float* Wk    = (const float*)d_in[6];
    const float* bk    = (const float*)d_in[7];
    const float* Wv    = (const float*)d_in[8];
    const float* bv    = (const float*)d_in[9];
    const float* Wp1   = (const float*)d_in[10];
    const float* bp1   = (const float*)d_in[11];
    const float* gp    = (const float*)d_in[12];
    const float* betap = (const float*)d_in[13];
    const float* Wp2   = (const float*)d_in[14];
    const float* bp2   = (const float*)d_in[15];
    const float* gw1   = (const float*)d_in[16];
    const float* bw1   = (const float*)d_in[17];
    const float* Ww1   = (const float*)d_in[18];
    const float* bww1  = (const float*)d_in[19];
    const float* gw2   = (const float*)d_in[20];
    const float* bw2   = (const float*)d_in[21];
    const float* Ww2   = (const float*)d_in[22];
    const float* bww2  = (const float*)d_in[23];
    float* out = (float*)d_out;

    k_zero  <<<1, 160>>>();
    k_qkv   <<<NPTS/32, 256>>>(x, Wq, bq, Wk, bk, Wv, bv);
    k_stats1<<<1184, 256>>>(p, idx, Wp1, bp1);
    k_stats2<<<dim3(592, 8), 256>>>(p, idx, Wp1, bp1, gp, betap, Wp2, bp2);
    k_proj  <<<2072, 256>>>(p, idx, Wp1, bp1, gp, betap, Wp2, bp2, gw1, bw1, Ww1, bww1);
    k_out   <<<NPTS/8, 256>>>(p, idx, Wp1, bp1, gp, betap, Wp2, bp2,
                              gw2, bw2, Ww2, bww2, out);
}

// round 9
// speedup vs baseline: 1.0374x; 1.0374x over previous
#include <cuda_runtime.h>
#include <math.h>

#define NPTS   100000
#define NSAMP  16
#define NELEM  (NPTS*NSAMP)
#define CC     64
#define CWW    8
#define EPSV   1e-5

// ---------------- device scratch ----------------
__device__ float  g_xq[NPTS*CC];
__device__ float  g_xk[NPTS*CC];
__device__ float  g_xv[NPTS*CC];
__device__ float  g_t [NELEM*CWW];
__device__ double g_stats[150];
// [0:3) s1  [3:6) q1  [6:70) s2  [70:134) q2  [134:142) s3  [142:150) q3

__global__ void k_zero() {
    if (threadIdx.x < 150) g_stats[threadIdx.x] = 0.0;
}

__device__ __forceinline__ void bn_affine_shared(int tid, int nch, int soff, int qoff,
        const float* __restrict__ gamma, const float* __restrict__ beta,
        float* sA, float* sB)
{
    if (tid < nch) {
        double m   = g_stats[soff + tid] * (1.0 / (double)NELEM);
        double v   = g_stats[qoff + tid] * (1.0 / (double)NELEM) - m * m;
        double inv = 1.0 / sqrt(v + (double)EPSV);
        double g   = (double)__ldg(gamma + tid);
        sA[tid] = (float)(g * inv);
        sB[tid] = (float)((double)__ldg(beta + tid) - m * inv * g);
    }
}

// ---------------- K1: fused QKV GEMM ----------------
__device__ __forceinline__ void qkv_phase(const float (*xs)[CC], float (*Ws)[CC],
        const float* __restrict__ W, const float* __restrict__ B,
        float* __restrict__ OUT, int n, int pt, int cg, int tid)
{
    __syncthreads();
    for (int i = tid; i < CC*CC; i += 256) (&Ws[0][0])[i] = __ldg(W + i);
    __syncthreads();
    float acc[8];
    #pragma unroll
    for (int j = 0; j < 8; j++) acc[j] = __ldg(B + cg + j);
    #pragma unroll 8
    for (int k = 0; k < CC; k++) {
        float xv = xs[pt][k];
        float4 wa = *(const float4*)&Ws[k][cg];
        float4 wb = *(const float4*)&Ws[k][cg+4];
        acc[0] = fmaf(xv, wa.x, acc[0]); acc[1] = fmaf(xv, wa.y, acc[1]);
        acc[2] = fmaf(xv, wa.z, acc[2]); acc[3] = fmaf(xv, wa.w, acc[3]);
        acc[4] = fmaf(xv, wb.x, acc[4]); acc[5] = fmaf(xv, wb.y, acc[5]);
        acc[6] = fmaf(xv, wb.z, acc[6]); acc[7] = fmaf(xv, wb.w, acc[7]);
    }
    float4* o = (float4*)(OUT + (size_t)n*CC + cg);
    o[0] = make_float4(acc[0], acc[1], acc[2], acc[3]);
    o[1] = make_float4(acc[4], acc[5], acc[6], acc[7]);
}

__global__ void __launch_bounds__(256) k_qkv(const float* __restrict__ x,
        const float* __restrict__ Wq, const float* __restrict__ bq,
        const float* __restrict__ Wk, const float* __restrict__ bk,
        const float* __restrict__ Wv, const float* __restrict__ bv)
{
    __shared__ float xs[32][CC];
    __shared__ float Ws[CC][CC];
    const int tid = threadIdx.x;
    const int n0  = blockIdx.x * 32;
    for (int i = tid; i < 32*CC; i += 256)
        xs[i >> 6][i & 63] = __ldg(x + (size_t)(n0 + (i >> 6))*CC + (i & 63));
    const int pt = tid >> 3;
    const int cg = (tid & 7) << 3;
    const int n  = n0 + pt;
    qkv_phase(xs, Ws, Wq, bq, g_xq, n, pt, cg, tid);
    qkv_phase(xs, Ws, Wk, bk, g_xk, n, pt, cg, tid);
    qkv_phase(xs, Ws, Wv, bv, g_xv, n, pt, cg, tid);
}

// ---------------- K2: BN1 stats ----------------
__global__ void __launch_bounds__(256) k_stats1(const float* __restrict__ p,
        const int* __restrict__ idx,
        const float* __restrict__ Wp1, const float* __restrict__ bp1)
{
    float w[9], b[3];
    #pragma unroll
    for (int i = 0; i < 9; i++) w[i] = __ldg(Wp1 + i);
    #pragma unroll
    for (int i = 0; i < 3; i++) b[i] = __ldg(bp1 + i);
    float s0=0.f,s1=0.f,s2=0.f,q0=0.f,q1=0.f,q2=0.f;
    const int stride = gridDim.x * blockDim.x;
    for (int e = blockIdx.x*blockDim.x + threadIdx.x; e < NELEM; e += stride) {
        int n = e >> 4;
        int j = __ldg(idx + e);
        float dx = __ldg(p + j*3 + 0) - __ldg(p + n*3 + 0);
        float dy = __ldg(p + j*3 + 1) - __ldg(p + n*3 + 1);
        float dz = __ldg(p + j*3 + 2) - __ldg(p + n*3 + 2);
        float h0 = fmaf(dx, w[0], fmaf(dy, w[3], fmaf(dz, w[6], b[0])));
        float h1 = fmaf(dx, w[1], fmaf(dy, w[4], fmaf(dz, w[7], b[1])));
        float h2 = fmaf(dx, w[2], fmaf(dy, w[5], fmaf(dz, w[8], b[2])));
        s0 += h0; q0 += h0*h0;
        s1 += h1; q1 += h1*h1;
        s2 += h2; q2 += h2*h2;
    }
    #pragma unroll
    for (int off = 16; off; off >>= 1) {
        s0 += __shfl_down_sync(0xffffffffu, s0, off); q0 += __shfl_down_sync(0xffffffffu, q0, off);
        s1 += __shfl_down_sync(0xffffffffu, s1, off); q1 += __shfl_down_sync(0xffffffffu, q1, off);
        s2 += __shfl_down_sync(0xffffffffu, s2, off); q2 += __shfl_down_sync(0xffffffffu, q2, off);
    }
    __shared__ double sh[6];
    if (threadIdx.x < 6) sh[threadIdx.x] = 0.0;
    __syncthreads();
    if ((threadIdx.x & 31) == 0) {
        atomicAdd(&sh[0], (double)s0); atomicAdd(&sh[1], (double)s1); atomicAdd(&sh[2], (double)s2);
        atomicAdd(&sh[3], (double)q0); atomicAdd(&sh[4], (double)q1); atomicAdd(&sh[5], (double)q2);
    }
    __syncthreads();
    if (threadIdx.x < 6) atomicAdd(&g_stats[threadIdx.x], sh[threadIdx.x]);
}

// ---------------- K3: BN2 stats — 16 lanes/element, coalesced row gathers ----------------
__global__ void __launch_bounds__(256) k_stats2(
        const float* __restrict__ p, const int* __restrict__ idx,
        const float* __restrict__ Wp1, const float* __restrict__ bp1,
        const float* __restrict__ gp, const float* __restrict__ betap,
        const float* __restrict__ Wp2, const float* __restrict__ bp2)
{
    const int tid  = threadIdx.x;
    const int lane = tid & 31;
    const int half = lane >> 4;
    const int cl   = lane & 15;
    __shared__ float  sA1[3], sB1[3];
    __shared__ double shd[128];
    bn_affine_shared(tid, 3, 0, 3, gp, betap, sA1, sB1);
    for (int i = tid; i < 128; i += 256) shd[i] = 0.0;
    __syncthreads();
    const float A1x=sA1[0], A1y=sA1[1], A1z=sA1[2];
    const float B1x=sB1[0], B1y=sB1[1], B1z=sB1[2];
    float w[9], b1r[3];
    #pragma unroll
    for (int i = 0; i < 9; i++) w[i] = __ldg(Wp1 + i);
    #pragma unroll
    for (int i = 0; i < 3; i++) b1r[i] = __ldg(bp1 + i);
    float4 pc[4];
    #pragma unroll
    for (int k2 = 0; k2 < 4; k2++) {
        int c = cl*4 + k2;
        pc[k2] = make_float4(__ldg(Wp2 + c), __ldg(Wp2 + 64 + c),
                             __ldg(Wp2 + 128 + c), __ldg(bp2 + c));
    }
    float s[4] = {0,0,0,0}, q[4] = {0,0,0,0};
    const int warpG = (blockIdx.x*256 + tid) >> 5;
    const int nW    = (gridDim.x*256) >> 5;
    for (int e0 = warpG*2; e0 < NELEM; e0 += nW*2) {
        const int e  = e0 + half;
        const int j  = __ldg(idx + e);
        const int nn = e >> 4;
        float dx = __ldg(p + j*3 + 0) - __ldg(p + nn*3 + 0);
        float dy = __ldg(p + j*3 + 1) - __ldg(p + nn*3 + 1);
        float dz = __ldg(p + j*3 + 2) - __ldg(p + nn*3 + 2);
        float h0 = fmaf(dx, w[0], fmaf(dy, w[3], fmaf(dz, w[6], b1r[0])));
        float h1 = fmaf(dx, w[1], fmaf(dy, w[4], fmaf(dz, w[7], b1r[1])));
        float h2 = fmaf(dx, w[2], fmaf(dy, w[5], fmaf(dz, w[8], b1r[2])));
        float a0 = fmaxf(fmaf(h0, A1x, B1x), 0.f);
        float a1 = fmaxf(fmaf(h1, A1y, B1y), 0.f);
        float a2 = fmaxf(fmaf(h2, A1z, B1z), 0.f);
        const float4 k4 = *(const float4*)(g_xk + (size_t)j*CC  + cl*4);
        const float4 q4 = *(const float4*)(g_xq + (size_t)nn*CC + cl*4);
        float r;
        r = k4.x - q4.x + fmaf(a0,pc[0].x,fmaf(a1,pc[0].y,fmaf(a2,pc[0].z,pc[0].w))); s[0]+=r; q[0]+=r*r;
        r = k4.y - q4.y + fmaf(a0,pc[1].x,fmaf(a1,pc[1].y,fmaf(a2,pc[1].z,pc[1].w))); s[1]+=r; q[1]+=r*r;
        r = k4.z - q4.z + fmaf(a0,pc[2].x,fmaf(a1,pc[2].y,fmaf(a2,pc[2].z,pc[2].w))); s[2]+=r; q[2]+=r*r;
        r = k4.w - q4.w + fmaf(a0,pc[3].x,fmaf(a1,pc[3].y,fmaf(a2,pc[3].z,pc[3].w))); s[3]+=r; q[3]+=r*r;
    }
    #pragma unroll
    for (int k2 = 0; k2 < 4; k2++) {
        s[k2] += __shfl_xor_sync(0xffffffffu, s[k2], 16);
        q[k2] += __shfl_xor_sync(0xffffffffu, q[k2], 16);
    }
    if (half == 0) {
        #pragma unroll
        for (int k2 = 0; k2 < 4; k2++) {
            atomicAdd(&shd[cl*4 + k2],      (double)s[k2]);
            atomicAdd(&shd[64 + cl*4 + k2], (double)q[k2]);
        }
    }
    __syncthreads();
    if (tid < 64)       atomicAdd(&g_stats[6  + tid],      shd[tid]);
    else if (tid < 128) atomicAdd(&g_stats[70 + tid - 64], shd[tid]);
}

// ---------------- K4: proj — 16 lanes/element, W1 in regs, butterfly reduce ----------------
__global__ void __launch_bounds__(256) k_proj(
        const float* __restrict__ p, const int* __restrict__ idx,
        const float* __restrict__ Wp1, const float* __restrict__ bp1,
        const float* __restrict__ gp, const float* __restrict__ betap,
        const float* __restrict__ Wp2, const float* __restrict__ bp2,
        const float* __restrict__ gw1, const float* __restrict__ bw1,
        const float* __restrict__ Ww1, const float* __restrict__ bww1)
{
    const int tid  = threadIdx.x;
    const int lane = tid & 31;
    const int half = lane >> 4;
    const int cl   = lane & 15;
    __shared__ float  sA1[3], sB1[3];
    __shared__ float  sA2[64], sB2[64];
    __shared__ double shd3[16];
    bn_affine_shared(tid, 3, 0, 3, gp, betap, sA1, sB1);
    if (tid < 64) {
        double m   = g_stats[6 + tid]  * (1.0 / (double)NELEM);
        double v   = g_stats[70 + tid] * (1.0 / (double)NELEM) - m*m;
        double inv = 1.0 / sqrt(v + (double)EPSV);
        double g   = (double)__ldg(gw1 + tid);
        sA2[tid] = (float)(g * inv);
        sB2[tid] = (float)((double)__ldg(bw1 + tid) - m*inv*g);
    }
    if (tid < 16) shd3[tid] = 0.0;
    __syncthreads();
    const float A1x=sA1[0], A1y=sA1[1], A1z=sA1[2];
    const float B1x=sB1[0], B1y=sB1[1], B1z=sB1[2];
    float w[9], b1r[3];
    #pragma unroll
    for (int i = 0; i < 9; i++) w[i] = __ldg(Wp1 + i);
    #pragma unroll
    for (int i = 0; i < 3; i++) b1r[i] = __ldg(bp1 + i);
    float4 pc[4]; float2 ab[4]; float4 w1a[4], w1b[4];
    #pragma unroll
    for (int k2 = 0; k2 < 4; k2++) {
        int c = cl*4 + k2;
        pc[k2]  = make_float4(__ldg(Wp2 + c), __ldg(Wp2 + 64 + c),
                              __ldg(Wp2 + 128 + c), __ldg(bp2 + c));
        ab[k2]  = make_float2(sA2[c], sB2[c]);
        w1a[k2] = *(const float4*)(Ww1 + c*8);
        w1b[k2] = *(const float4*)(Ww1 + c*8 + 4);
    }
    const float bias = __ldg(bww1 + (cl & 7));
    float s3 = 0.f, q3 = 0.f;
    const int warpG = (blockIdx.x*256 + tid) >> 5;
    const int nW    = (gridDim.x*256) >> 5;
    for (int e0 = warpG*2; e0 < NELEM; e0 += nW*2) {
        const int e  = e0 + half;
        const int j  = __ldg(idx + e);
        const int nn = e >> 4;
        float dx = __ldg(p + j*3 + 0) - __ldg(p + nn*3 + 0);
        float dy = __ldg(p + j*3 + 1) - __ldg(p + nn*3 + 1);
        float dz = __ldg(p + j*3 + 2) - __ldg(p + nn*3 + 2);
        float h0 = fmaf(dx, w[0], fmaf(dy, w[3], fmaf(dz, w[6], b1r[0])));
        float h1 = fmaf(dx, w[1], fmaf(dy, w[4], fmaf(dz, w[7], b1r[1])));
        float h2 = fmaf(dx, w[2], fmaf(dy, w[5], fmaf(dz, w[8], b1r[2])));
        float a0 = fmaxf(fmaf(h0, A1x, B1x), 0.f);
        float a1 = fmaxf(fmaf(h1, A1y, B1y), 0.f);
        float a2 = fmaxf(fmaf(h2, A1z, B1z), 0.f);
        const float4 k4 = *(const float4*)(g_xk + (size_t)j*CC  + cl*4);
        const float4 q4 = *(const float4*)(g_xq + (size_t)nn*CC + cl*4);
        float kk[4] = {k4.x, k4.y, k4.z, k4.w};
        float qq[4] = {q4.x, q4.y, q4.z, q4.w};
        float acc[8] = {0,0,0,0,0,0,0,0};
        #pragma unroll
        for (int k2 = 0; k2 < 4; k2++) {
            float r = kk[k2] - qq[k2] +
                      fmaf(a0, pc[k2].x, fmaf(a1, pc[k2].y, fmaf(a2, pc[k2].z, pc[k2].w)));
            float y = fmaxf(fmaf(r, ab[k2].x, ab[k2].y), 0.f);
            acc[0] = fmaf(y, w1a[k2].x, acc[0]); acc[1] = fmaf(y, w1a[k2].y, acc[1]);
            acc[2] = fmaf(y, w1a[k2].z, acc[2]); acc[3] = fmaf(y, w1a[k2].w, acc[3]);
            acc[4] = fmaf(y, w1b[k2].x, acc[4]); acc[5] = fmaf(y, w1b[k2].y, acc[5]);
            acc[6] = fmaf(y, w1b[k2].z, acc[6]); acc[7] = fmaf(y, w1b[k2].w, acc[7]);
        }
        #pragma unroll
        for (int m = 1; m <= 8; m <<= 1) {
            #pragma unroll
            for (int o = 0; o < 8; o++)
                acc[o] += __shfl_xor_sync(0xffffffffu, acc[o], m);
        }
        if (cl < 8) {
            float v = acc[cl] + bias;
            g_t[(size_t)e*8 + cl] = v;
            s3 += v; q3 += v*v;
        }
    }
    s3 += __shfl_xor_sync(0xffffffffu, s3, 16);
    q3 += __shfl_xor_sync(0xffffffffu, q3, 16);
    if (lane < 8) {
        atomicAdd(&shd3[lane],     (double)s3);
        atomicAdd(&shd3[8 + lane], (double)q3);
    }
    __syncthreads();
    if (tid < 16) atomicAdd(&g_stats[134 + tid], shd3[tid]);
}

// ---------------- K5: softmax + weighted sum ----------------
__global__ void __launch_bounds__(256) k_out(
        const float* __restrict__ p, const int* __restrict__ idx,
        const float* __restrict__ Wp1, const float* __restrict__ bp1,
        const float* __restrict__ gp, const float* __restrict__ betap,
        const float* __restrict__ Wp2, const float* __restrict__ bp2,
        const float* __restrict__ gw2, const float* __restrict__ bw2,
        const float* __restrict__ Ww2, const float* __restrict__ bww2,
        float* __restrict__ out)
{
    const int tid  = threadIdx.x;
    const int lane = tid & 31;
    const int warp = tid >> 5;
    const int n    = blockIdx.x * 8 + warp;
    const int ci   = lane >> 2;
    const int tq   = lane & 3;

    __shared__ float sA1[3], sB1[3], sA3[8], sB3[8];
    bn_affine_shared(tid, 3, 0, 3, gp, betap, sA1, sB1);
    bn_affine_shared(tid, 8, 134, 142, gw2, bw2, sA3, sB3);
    __syncthreads();
    const float A1x=sA1[0], A1y=sA1[1], A1z=sA1[2];
    const float B1x=sB1[0], B1y=sB1[1], B1z=sB1[2];
    float A3[8], B3[8], w2c[8];
    #pragma unroll
    for (int k = 0; k < 8; k++) {
        A3[k] = sA3[k]; B3[k] = sB3[k];
        w2c[k] = __ldg(Ww2 + k*8 + ci);
    }
    const float bw2c = __ldg(bww2 + ci);
    float w1r[9], b1r[3];
    #pragma unroll
    for (int i = 0; i < 9; i++) w1r[i] = __ldg(Wp1 + i);
    #pragma unroll
    for (int i = 0; i < 3; i++) b1r[i] = __ldg(bp1 + i);
    float p20[8], p21[8], p22[8], pbv[8];
    #pragma unroll
    for (int s = 0; s < 8; s++) {
        int c = s*8 + ci;
        p20[s] = __ldg(Wp2 + c);       p21[s] = __ldg(Wp2 + 64 + c);
        p22[s] = __ldg(Wp2 + 128 + c); pbv[s] = __ldg(bp2 + c);
    }
    const float px = __ldg(p + n*3 + 0), py = __ldg(p + n*3 + 1), pz = __ldg(p + n*3 + 2);

    int   js[4];
    float a0s[4], a1s[4], a2s[4], L[4];
    #pragma unroll
    for (int u = 0; u < 4; u++) {
        int t = tq*4 + u;
        int e = n*16 + t;
        int j = __ldg(idx + e);
        js[u] = j;
        float dx = __ldg(p + j*3 + 0) - px;
        float dy = __ldg(p + j*3 + 1) - py;
        float dz = __ldg(p + j*3 + 2) - pz;
        float h0 = fmaf(dx, w1r[0], fmaf(dy, w1r[3], fmaf(dz, w1r[6], b1r[0])));
        float h1 = fmaf(dx, w1r[1], fmaf(dy, w1r[4], fmaf(dz, w1r[7], b1r[1])));
        float h2 = fmaf(dx, w1r[2], fmaf(dy, w1r[5], fmaf(dz, w1r[8], b1r[2])));
        a0s[u] = fmaxf(fmaf(h0, A1x, B1x), 0.f);
        a1s[u] = fmaxf(fmaf(h1, A1y, B1y), 0.f);
        a2s[u] = fmaxf(fmaf(h2, A1z, B1z), 0.f);
        const float4 ta = *(const float4*)(g_t + (size_t)e*8);
        const float4 tb = *(const float4*)(g_t + (size_t)e*8 + 4);
        float lg = bw2c;
        lg = fmaf(fmaxf(fmaf(ta.x, A3[0], B3[0]), 0.f), w2c[0], lg);
        lg = fmaf(fmaxf(fmaf(ta.y, A3[1], B3[1]), 0.f), w2c[1], lg);
        lg = fmaf(fmaxf(fmaf(ta.z, A3[2], B3[2]), 0.f), w2c[2], lg);
        lg = fmaf(fmaxf(fmaf(ta.w, A3[3], B3[3]), 0.f), w2c[3], lg);
        lg = fmaf(fmaxf(fmaf(tb.x, A3[4], B3[4]), 0.f), w2c[4], lg);
        lg = fmaf(fmaxf(fmaf(tb.y, A3[5], B3[5]), 0.f), w2c[5], lg);
        lg = fmaf(fmaxf(fmaf(tb.z, A3[6], B3[6]), 0.f), w2c[6], lg);
        lg = fmaf(fmaxf(fmaf(tb.w, A3[7], B3[7]), 0.f), w2c[7], lg);
        L[u] = lg;
    }
    float mx = fmaxf(fmaxf(L[0], L[1]), fmaxf(L[2], L[3]));
    mx = fmaxf(mx, __shfl_xor_sync(0xffffffffu, mx, 1));
    mx = fmaxf(mx, __shfl_xor_sync(0xffffffffu, mx, 2));
    float sum = 0.f;
    #pragma unroll
    for (int u = 0; u < 4; u++) { L[u] = expf(L[u] - mx); sum += L[u]; }
    sum += __shfl_xor_sync(0xffffffffu, sum, 1);
    sum += __shfl_xor_sync(0xffffffffu, sum, 2);
    const float rs = 1.f / sum;

    float acc[8] = {0,0,0,0,0,0,0,0};
    #pragma unroll
    for (int u = 0; u < 4; u++) {
        float wv = L[u] * rs;
        const float* xr = g_xv + (size_t)js[u]*CC;
        float a0 = a0s[u], a1 = a1s[u], a2 = a2s[u];
        #pragma unroll
        for (int s = 0; s < 8; s++) {
            float pr = fmaf(a0, p20[s], fmaf(a1, p21[s], fmaf(a2, p22[s], pbv[s])));
            acc[s] = fmaf(__ldg(xr + s*8 + ci) + pr, wv, acc[s]);
        }
    }
    #pragma unroll
    for (int s = 0; s < 8; s++) {
        acc[s] += __shfl_xor_sync(0xffffffffu, acc[s], 1);
        acc[s] += __shfl_xor_sync(0xffffffffu, acc[s], 2);
    }
    __shared__ float smout[8][64];
    if (tq == 0) {
        #pragma unroll
        for (int s = 0; s < 8; s++) smout[warp][s*8 + ci] = acc[s];
    }
    __syncthreads();
    const int nb = blockIdx.x * 8;
    for (int i2 = tid; i2 < 8*64; i2 += 256)
        out[(size_t)nb*64 + i2] = (&smout[0][0])[i2];
}

// ---------------- host ----------------
extern "C" void kernel_launch(void* const* d_in, const int* in_sizes, int n_in,
                              void* d_out, int out_size)
{
    const float* p     = (const float*)d_in[0];
    const float* x     = (const float*)d_in[1];
    const int*   idx   = (const int*)  d_in[3];
    const float* Wq    = (const float*)d_in[4];
    const float* bq    = (const float*)d_in[5];
    const float* Wk    = (const float*)d_in[6];
    const float* bk    = (const float*)d_in[7];
    const float* Wv    = (const float*)d_in[8];
    const float* bv    = (const float*)d_in[9];
    const float* Wp1   = (const float*)d_in[10];
    const float* bp1   = (const float*)d_in[11];
    const float* gp    = (const float*)d_in[12];
    const float* betap = (const float*)d_in[13];
    const float* Wp2   = (const float*)d_in[14];
    const float* bp2   = (const float*)d_in[15];
    const float* gw1   = (const float*)d_in[16];
    const float* bw1   = (const float*)d_in[17];
    const float* Ww1   = (const float*)d_in[18];
    const float* bww1  = (const float*)d_in[19];
    const float* gw2   = (const float*)d_in[20];
    const float* bw2   = (const float*)d_in[21];
    const float* Ww2   = (const float*)d_in[22];
    const float* bww2  = (const float*)d_in[23];
    float* out = (float*)d_out;

    k_zero  <<<1, 160>>>();
    k_qkv   <<<NPTS/32, 256>>>(x, Wq, bq, Wk, bk, Wv, bv);
    k_stats1<<<1184, 256>>>(p, idx, Wp1, bp1);
    k_stats2<<<2368, 256>>>(p, idx, Wp1, bp1, gp, betap, Wp2, bp2);
    k_proj  <<<2368, 256>>>(p, idx, Wp1, bp1, gp, betap, Wp2, bp2, gw1, bw1, Ww1, bww1);
    k_out   <<<NPTS/8, 256>>>(p, idx, Wp1, bp1, gp, betap, Wp2, bp2,
                              gw2, bw2, Ww2, bww2, out);
}

// round 11
// speedup vs baseline: 1.0988x; 1.0592x over previous
#include <cuda_runtime.h>
#include <math.h>

#define NPTS   100000
#define NSAMP  16
#define NELEM  (NPTS*NSAMP)
#define CC     64
#define CWW    8
#define EPSV   1e-5

// ---------------- device scratch ----------------
__device__ float  g_xq[NPTS*CC];
__device__ float  g_xk[NPTS*CC];
__device__ float  g_xv[NPTS*CC];
__device__ float  g_t [NELEM*CWW];
__device__ float  g_h [NELEM*3];     // planar: h after k_stats1, a=relu(bn1(h)) after k_stats2
__device__ double g_stats[150];
// [0:3) s1  [3:6) q1  [6:70) s2  [70:134) q2  [134:142) s3  [142:150) q3

__global__ void k_zero() {
    if (threadIdx.x < 150) g_stats[threadIdx.x] = 0.0;
}

__device__ __forceinline__ void bn_affine_shared(int tid, int nch, int soff, int qoff,
        const float* __restrict__ gamma, const float* __restrict__ beta,
        float* sA, float* sB)
{
    if (tid < nch) {
        double m   = g_stats[soff + tid] * (1.0 / (double)NELEM);
        double v   = g_stats[qoff + tid] * (1.0 / (double)NELEM) - m * m;
        double inv = 1.0 / sqrt(v + (double)EPSV);
        double g   = (double)__ldg(gamma + tid);
        sA[tid] = (float)(g * inv);
        sB[tid] = (float)((double)__ldg(beta + tid) - m * inv * g);
    }
}

// ---------------- K1: fused QKV GEMM ----------------
__device__ __forceinline__ void qkv_phase(const float (*xs)[CC], float (*Ws)[CC],
        const float* __restrict__ W, const float* __restrict__ B,
        float* __restrict__ OUT, int n, int pt, int cg, int tid)
{
    __syncthreads();
    for (int i = tid; i < CC*CC; i += 256) (&Ws[0][0])[i] = __ldg(W + i);
    __syncthreads();
    float acc[8];
    #pragma unroll
    for (int j = 0; j < 8; j++) acc[j] = __ldg(B + cg + j);
    #pragma unroll 8
    for (int k = 0; k < CC; k++) {
        float xv = xs[pt][k];
        float4 wa = *(const float4*)&Ws[k][cg];
        float4 wb = *(const float4*)&Ws[k][cg+4];
        acc[0] = fmaf(xv, wa.x, acc[0]); acc[1] = fmaf(xv, wa.y, acc[1]);
        acc[2] = fmaf(xv, wa.z, acc[2]); acc[3] = fmaf(xv, wa.w, acc[3]);
        acc[4] = fmaf(xv, wb.x, acc[4]); acc[5] = fmaf(xv, wb.y, acc[5]);
        acc[6] = fmaf(xv, wb.z, acc[6]); acc[7] = fmaf(xv, wb.w, acc[7]);
    }
    float4* o = (float4*)(OUT + (size_t)n*CC + cg);
    o[0] = make_float4(acc[0], acc[1], acc[2], acc[3]);
    o[1] = make_float4(acc[4], acc[5], acc[6], acc[7]);
}

__global__ void __launch_bounds__(256) k_qkv(const float* __restrict__ x,
        const float* __restrict__ Wq, const float* __restrict__ bq,
        const float* __restrict__ Wk, const float* __restrict__ bk,
        const float* __restrict__ Wv, const float* __restrict__ bv)
{
    __shared__ float xs[32][CC];
    __shared__ float Ws[CC][CC];
    const int tid = threadIdx.x;
    const int n0  = blockIdx.x * 32;
    for (int i = tid; i < 32*CC; i += 256)
        xs[i >> 6][i & 63] = __ldg(x + (size_t)(n0 + (i >> 6))*CC + (i & 63));
    const int pt = tid >> 3;
    const int cg = (tid & 7) << 3;
    const int n  = n0 + pt;
    qkv_phase(xs, Ws, Wq, bq, g_xq, n, pt, cg, tid);
    qkv_phase(xs, Ws, Wk, bk, g_xk, n, pt, cg, tid);
    qkv_phase(xs, Ws, Wv, bv, g_xv, n, pt, cg, tid);
}

// ---------------- K2: BN1 stats + materialize h ----------------
__global__ void __launch_bounds__(256) k_stats1(const float* __restrict__ p,
        const int* __restrict__ idx,
        const float* __restrict__ Wp1, const float* __restrict__ bp1)
{
    float w[9], b[3];
    #pragma unroll
    for (int i = 0; i < 9; i++) w[i] = __ldg(Wp1 + i);
    #pragma unroll
    for (int i = 0; i < 3; i++) b[i] = __ldg(bp1 + i);
    float s0=0.f,s1=0.f,s2=0.f,q0=0.f,q1=0.f,q2=0.f;
    const int stride = gridDim.x * blockDim.x;
    for (int e = blockIdx.x*blockDim.x + threadIdx.x; e < NELEM; e += stride) {
        int n = e >> 4;
        int j = __ldg(idx + e);
        float dx = __ldg(p + j*3 + 0) - __ldg(p + n*3 + 0);
        float dy = __ldg(p + j*3 + 1) - __ldg(p + n*3 + 1);
        float dz = __ldg(p + j*3 + 2) - __ldg(p + n*3 + 2);
        float h0 = fmaf(dx, w[0], fmaf(dy, w[3], fmaf(dz, w[6], b[0])));
        float h1 = fmaf(dx, w[1], fmaf(dy, w[4], fmaf(dz, w[7], b[1])));
        float h2 = fmaf(dx, w[2], fmaf(dy, w[5], fmaf(dz, w[8], b[2])));
        g_h[e]           = h0;
        g_h[NELEM + e]   = h1;
        g_h[2*NELEM + e] = h2;
        s0 += h0; q0 += h0*h0;
        s1 += h1; q1 += h1*h1;
        s2 += h2; q2 += h2*h2;
    }
    #pragma unroll
    for (int off = 16; off; off >>= 1) {
        s0 += __shfl_down_sync(0xffffffffu, s0, off); q0 += __shfl_down_sync(0xffffffffu, q0, off);
        s1 += __shfl_down_sync(0xffffffffu, s1, off); q1 += __shfl_down_sync(0xffffffffu, q1, off);
        s2 += __shfl_down_sync(0xffffffffu, s2, off); q2 += __shfl_down_sync(0xffffffffu, q2, off);
    }
    __shared__ double sh[6];
    if (threadIdx.x < 6) sh[threadIdx.x] = 0.0;
    __syncthreads();
    if ((threadIdx.x & 31) == 0) {
        atomicAdd(&sh[0], (double)s0); atomicAdd(&sh[1], (double)s1); atomicAdd(&sh[2], (double)s2);
        atomicAdd(&sh[3], (double)q0); atomicAdd(&sh[4], (double)q1); atomicAdd(&sh[5], (double)q2);
    }
    __syncthreads();
    if (threadIdx.x < 6) atomicAdd(&g_stats[threadIdx.x], sh[threadIdx.x]);
}

// ---------------- K3: BN2 stats — load h, store a in place, coalesced gathers ----------------
__global__ void __launch_bounds__(256, 4) k_stats2(
        const int* __restrict__ idx,
        const float* __restrict__ gp, const float* __restrict__ betap,
        const float* __restrict__ Wp2, const float* __restrict__ bp2)
{
    const int tid  = threadIdx.x;
    const int lane = tid & 31;
    const int half = lane >> 4;
    const int cl   = lane & 15;
    __shared__ float  sA1[3], sB1[3];
    __shared__ double shd[128];
    bn_affine_shared(tid, 3, 0, 3, gp, betap, sA1, sB1);
    for (int i = tid; i < 128; i += 256) shd[i] = 0.0;
    __syncthreads();
    const float A1x=sA1[0], A1y=sA1[1], A1z=sA1[2];
    const float B1x=sB1[0], B1y=sB1[1], B1z=sB1[2];
    float4 pc[4];
    #pragma unroll
    for (int k2 = 0; k2 < 4; k2++) {
        int c = cl*4 + k2;
        pc[k2] = make_float4(__ldg(Wp2 + c), __ldg(Wp2 + 64 + c),
                             __ldg(Wp2 + 128 + c), __ldg(bp2 + c));
    }
    float s[4] = {0,0,0,0}, q[4] = {0,0,0,0};
    const int warpG = (blockIdx.x*256 + tid) >> 5;
    const int nW    = (gridDim.x*256) >> 5;
    for (int e0 = warpG*2; e0 < NELEM; e0 += nW*2) {
        const int e = e0 + half;
        const int j = __ldg(idx + e);
        float h0 = __ldg(g_h + e);
        float h1 = __ldg(g_h + NELEM + e);
        float h2 = __ldg(g_h + 2*NELEM + e);
        float a0 = fmaxf(fmaf(h0, A1x, B1x), 0.f);
        float a1 = fmaxf(fmaf(h1, A1y, B1y), 0.f);
        float a2 = fmaxf(fmaf(h2, A1z, B1z), 0.f);
        if (cl == 0) {
            g_h[e]           = a0;
            g_h[NELEM + e]   = a1;
            g_h[2*NELEM + e] = a2;
        }
        const int nn = e >> 4;
        const float4 k4 = *(const float4*)(g_xk + (size_t)j*CC  + cl*4);
        const float4 q4 = *(const float4*)(g_xq + (size_t)nn*CC + cl*4);
        float r;
        r = k4.x - q4.x + fmaf(a0,pc[0].x,fmaf(a1,pc[0].y,fmaf(a2,pc[0].z,pc[0].w))); s[0]+=r; q[0]+=r*r;
        r = k4.y - q4.y + fmaf(a0,pc[1].x,fmaf(a1,pc[1].y,fmaf(a2,pc[1].z,pc[1].w))); s[1]+=r; q[1]+=r*r;
        r = k4.z - q4.z + fmaf(a0,pc[2].x,fmaf(a1,pc[2].y,fmaf(a2,pc[2].z,pc[2].w))); s[2]+=r; q[2]+=r*r;
        r = k4.w - q4.w + fmaf(a0,pc[3].x,fmaf(a1,pc[3].y,fmaf(a2,pc[3].z,pc[3].w))); s[3]+=r; q[3]+=r*r;
    }
    #pragma unroll
    for (int k2 = 0; k2 < 4; k2++) {
        s[k2] += __shfl_xor_sync(0xffffffffu, s[k2], 16);
        q[k2] += __shfl_xor_sync(0xffffffffu, q[k2], 16);
    }
    if (half == 0) {
        #pragma unroll
        for (int k2 = 0; k2 < 4; k2++) {
            atomicAdd(&shd[cl*4 + k2],      (double)s[k2]);
            atomicAdd(&shd[64 + cl*4 + k2], (double)q[k2]);
        }
    }
    __syncthreads();
    if (tid < 64)       atomicAdd(&g_stats[6  + tid],      shd[tid]);
    else if (tid < 128) atomicAdd(&g_stats[70 + tid - 64], shd[tid]);
}

// ---------------- K4: proj — load a, W1 in regs, butterfly reduce ----------------
__global__ void __launch_bounds__(256) k_proj(
        const int* __restrict__ idx,
        const float* __restrict__ Wp2, const float* __restrict__ bp2,
        const float* __restrict__ gw1, const float* __restrict__ bw1,
        const float* __restrict__ Ww1, const float* __restrict__ bww1)
{
    const int tid  = threadIdx.x;
    const int lane = tid & 31;
    const int half = lane >> 4;
    const int cl   = lane & 15;
    __shared__ float  sA2[64], sB2[64];
    __shared__ double shd3[16];
    if (tid < 64) {
        double m   = g_stats[6 + tid]  * (1.0 / (double)NELEM);
        double v   = g_stats[70 + tid] * (1.0 / (double)NELEM) - m*m;
        double inv = 1.0 / sqrt(v + (double)EPSV);
        double g   = (double)__ldg(gw1 + tid);
        sA2[tid] = (float)(g * inv);
        sB2[tid] = (float)((double)__ldg(bw1 + tid) - m*inv*g);
    }
    if (tid < 16) shd3[tid] = 0.0;
    __syncthreads();
    float4 pc[4]; float2 ab[4]; float4 w1a[4], w1b[4];
    #pragma unroll
    for (int k2 = 0; k2 < 4; k2++) {
        int c = cl*4 + k2;
        pc[k2]  = make_float4(__ldg(Wp2 + c), __ldg(Wp2 + 64 + c),
                              __ldg(Wp2 + 128 + c), __ldg(bp2 + c));
        ab[k2]  = make_float2(sA2[c], sB2[c]);
        w1a[k2] = *(const float4*)(Ww1 + c*8);
        w1b[k2] = *(const float4*)(Ww1 + c*8 + 4);
    }
    const float bias = __ldg(bww1 + (cl & 7));
    float s3 = 0.f, q3 = 0.f;
    const int warpG = (blockIdx.x*256 + tid) >> 5;
    const int nW    = (gridDim.x*256) >> 5;
    for (int e0 = warpG*2; e0 < NELEM; e0 += nW*2) {
        const int e = e0 + half;
        const int j = __ldg(idx + e);
        float a0 = __ldg(g_h + e);
        float a1 = __ldg(g_h + NELEM + e);
        float a2 = __ldg(g_h + 2*NELEM + e);
        const int nn = e >> 4;
        const float4 k4 = *(const float4*)(g_xk + (size_t)j*CC  + cl*4);
        const float4 q4 = *(const float4*)(g_xq + (size_t)nn*CC + cl*4);
        float kk[4] = {k4.x, k4.y, k4.z, k4.w};
        float qq[4] = {q4.x, q4.y, q4.z, q4.w};
        float acc[8] = {0,0,0,0,0,0,0,0};
        #pragma unroll
        for (int k2 = 0; k2 < 4; k2++) {
            float r = kk[k2] - qq[k2] +
                      fmaf(a0, pc[k2].x, fmaf(a1, pc[k2].y, fmaf(a2, pc[k2].z, pc[k2].w)));
            float y = fmaxf(fmaf(r, ab[k2].x, ab[k2].y), 0.f);
            acc[0] = fmaf(y, w1a[k2].x, acc[0]); acc[1] = fmaf(y, w1a[k2].y, acc[1]);
            acc[2] = fmaf(y, w1a[k2].z, acc[2]); acc[3] = fmaf(y, w1a[k2].w, acc[3]);
            acc[4] = fmaf(y, w1b[k2].x, acc[4]); acc[5] = fmaf(y, w1b[k2].y, acc[5]);
            acc[6] = fmaf(y, w1b[k2].z, acc[6]); acc[7] = fmaf(y, w1b[k2].w, acc[7]);
        }
        #pragma unroll
        for (int m = 1; m <= 8; m <<= 1) {
            #pragma unroll
            for (int o = 0; o < 8; o++)
                acc[o] += __shfl_xor_sync(0xffffffffu, acc[o], m);
        }
        if (cl < 8) {
            float v = acc[cl] + bias;
            g_t[(size_t)e*8 + cl] = v;
            s3 += v; q3 += v*v;
        }
    }
    s3 += __shfl_xor_sync(0xffffffffu, s3, 16);
    q3 += __shfl_xor_sync(0xffffffffu, q3, 16);
    if (lane < 8) {
        atomicAdd(&shd3[lane],     (double)s3);
        atomicAdd(&shd3[8 + lane], (double)q3);
    }
    __syncthreads();
    if (tid < 16) atomicAdd(&g_stats[134 + tid], shd3[tid]);
}

// ---------------- K5: softmax + weighted sum ----------------
__global__ void __launch_bounds__(256) k_out(
        const int* __restrict__ idx,
        const float* __restrict__ Wp2, const float* __restrict__ bp2,
        const float* __restrict__ gw2, const float* __restrict__ bw2,
        const float* __restrict__ Ww2, const float* __restrict__ bww2,
        float* __restrict__ out)
{
    const int tid  = threadIdx.x;
    const int lane = tid & 31;
    const int warp = tid >> 5;
    const int n    = blockIdx.x * 8 + warp;
    const int ci   = lane >> 2;
    const int tq   = lane & 3;

    __shared__ float sA3[8], sB3[8];
    bn_affine_shared(tid, 8, 134, 142, gw2, bw2, sA3, sB3);
    __syncthreads();
    float A3[8], B3[8], w2c[8];
    #pragma unroll
    for (int k = 0; k < 8; k++) {
        A3[k] = sA3[k]; B3[k] = sB3[k];
        w2c[k] = __ldg(Ww2 + k*8 + ci);
    }
    const float bw2c = __ldg(bww2 + ci);
    float p20[8], p21[8], p22[8], pbv[8];
    #pragma unroll
    for (int s = 0; s < 8; s++) {
        int c = s*8 + ci;
        p20[s] = __ldg(Wp2 + c);       p21[s] = __ldg(Wp2 + 64 + c);
        p22[s] = __ldg(Wp2 + 128 + c); pbv[s] = __ldg(bp2 + c);
    }

    int   js[4];
    float a0s[4], a1s[4], a2s[4], L[4];
    #pragma unroll
    for (int u = 0; u < 4; u++) {
        int t = tq*4 + u;
        int e = n*16 + t;
        int j = __ldg(idx + e);
        js[u] = j;
        a0s[u] = __ldg(g_h + e);
        a1s[u] = __ldg(g_h + NELEM + e);
        a2s[u] = __ldg(g_h + 2*NELEM + e);
        const float4 ta = *(const float4*)(g_t + (size_t)e*8);
        const float4 tb = *(const float4*)(g_t + (size_t)e*8 + 4);
        float lg = bw2c;
        lg = fmaf(fmaxf(fmaf(ta.x, A3[0], B3[0]), 0.f), w2c[0], lg);
        lg = fmaf(fmaxf(fmaf(ta.y, A3[1], B3[1]), 0.f), w2c[1], lg);
        lg = fmaf(fmaxf(fmaf(ta.z, A3[2], B3[2]), 0.f), w2c[2], lg);
        lg = fmaf(fmaxf(fmaf(ta.w, A3[3], B3[3]), 0.f), w2c[3], lg);
        lg = fmaf(fmaxf(fmaf(tb.x, A3[4], B3[4]), 0.f), w2c[4], lg);
        lg = fmaf(fmaxf(fmaf(tb.y, A3[5], B3[5]), 0.f), w2c[5], lg);
        lg = fmaf(fmaxf(fmaf(tb.z, A3[6], B3[6]), 0.f), w2c[6], lg);
        lg = fmaf(fmaxf(fmaf(tb.w, A3[7], B3[7]), 0.f), w2c[7], lg);
        L[u] = lg;
    }
    float mx = fmaxf(fmaxf(L[0], L[1]), fmaxf(L[2], L[3]));
    mx = fmaxf(mx, __shfl_xor_sync(0xffffffffu, mx, 1));
    mx = fmaxf(mx, __shfl_xor_sync(0xffffffffu, mx, 2));
    float sum = 0.f;
    #pragma unroll
    for (int u = 0; u < 4; u++) { L[u] = expf(L[u] - mx); sum += L[u]; }
    sum += __shfl_xor_sync(0xffffffffu, sum, 1);
    sum += __shfl_xor_sync(0xffffffffu, sum, 2);
    const float rs = 1.f / sum;

    float acc[8] = {0,0,0,0,0,0,0,0};
    #pragma unroll
    for (int u = 0; u < 4; u++) {
        float wv = L[u] * rs;
        const float* xr = g_xv + (size_t)js[u]*CC;
        float a0 = a0s[u], a1 = a1s[u], a2 = a2s[u];
        #pragma unroll
        for (int s = 0; s < 8; s++) {
            float pr = fmaf(a0, p20[s], fmaf(a1, p21[s], fmaf(a2, p22[s], pbv[s])));
            acc[s] = fmaf(__ldg(xr + s*8 + ci) + pr, wv, acc[s]);
        }
    }
    #pragma unroll
    for (int s = 0; s < 8; s++) {
        acc[s] += __shfl_xor_sync(0xffffffffu, acc[s], 1);
        acc[s] += __shfl_xor_sync(0xffffffffu, acc[s], 2);
    }
    __shared__ float smout[8][64];
    if (tq == 0) {
        #pragma unroll
        for (int s = 0; s < 8; s++) smout[warp][s*8 + ci] = acc[s];
    }
    __syncthreads();
    const int nb = blockIdx.x * 8;
    for (int i2 = tid; i2 < 8*64; i2 += 256)
        out[(size_t)nb*64 + i2] = (&smout[0][0])[i2];
}

// ---------------- host ----------------
extern "C" void kernel_launch(void* const* d_in, const int* in_sizes, int n_in,
                              void* d_out, int out_size)
{
    const float* p     = (const float*)d_in[0];
    const float* x     = (const float*)d_in[1];
    const int*   idx   = (const int*)  d_in[3];
    const float* Wq    = (const float*)d_in[4];
    const float* bq    = (const float*)d_in[5];
    const float* Wk    = (const float*)d_in[6];
    const float* bk    = (const float*)d_in[7];
    const float* Wv    = (const float*)d_in[8];
    const float* bv    = (const float*)d_in[9];
    const float* Wp1   = (const float*)d_in[10];
    const float* bp1   = (const float*)d_in[11];
    const float* gp    = (const float*)d_in[12];
    const float* betap = (const float*)d_in[13];
    const float* Wp2   = (const float*)d_in[14];
    const float* bp2   = (const float*)d_in[15];
    const float* gw1   = (const float*)d_in[16];
    const float* bw1   = (const float*)d_in[17];
    const float* Ww1   = (const float*)d_in[18];
    const float* bww1  = (const float*)d_in[19];
    const float* gw2   = (const float*)d_in[20];
    const float* bw2   = (const float*)d_in[21];
    const float* Ww2   = (const float*)d_in[22];
    const float* bww2  = (const float*)d_in[23];
    float* out = (float*)d_out;

    k_zero  <<<1, 160>>>();
    k_qkv   <<<NPTS/32, 256>>>(x, Wq, bq, Wk, bk, Wv, bv);
    k_stats1<<<1184, 256>>>(p, idx, Wp1, bp1);
    k_stats2<<<2368, 256>>>(idx, gp, betap, Wp2, bp2);
    k_proj  <<<2368, 256>>>(idx, Wp2, bp2, gw1, bw1, Ww1, bww1);
    k_out   <<<NPTS/8, 256>>>(idx, Wp2, bp2, gw2, bw2, Ww2, bww2, out);
}